// round 2
// baseline (speedup 1.0000x reference)
#include <cuda_runtime.h>

#define HH 128
#define WW 128
#define CC 64
#define OO 64
#define BB 2
#define KK9 9
#define HWSZ (HH*WW)

#define PIX 64          // pixels per CTA in main kernel
#define CCH 16          // channels per chunk
#define KKC (CCH*KK9)   // 144 rows per chunk

// ---------------- scratch (__device__ globals: no allocation allowed) ----------
__device__ int4   g_sidx[BB*HWSZ*KK9];   // clamped gather indices per (b,pix,k)
__device__ float4 g_swgt[BB*HWSZ*KK9];   // mask-folded bilinear corner weights
__device__ float  g_wt[CC*KK9*OO];       // weight transposed to [c*9+k][o]

// ---------------- K0: weight transpose ----------------------------------------
__global__ void transpose_w_kernel(const float* __restrict__ wsrc) {
    int i = blockIdx.x * 256 + threadIdx.x;
    if (i < OO*CC*KK9) {
        int o  = i / (CC*KK9);
        int ck = i % (CC*KK9);
        g_wt[ck*OO + o] = wsrc[i];
    }
}

// ---------------- K1: offset conv + bilinear precompute ------------------------
// CTA = (b, h) row, 128 threads = w. Each thread: 27 conv outputs in registers.
// smem: offset weights reorganized [c][tap][28] (27 used, padded for float4).
__global__ __launch_bounds__(128) void offset_kernel(
    const float* __restrict__ x,
    const float* __restrict__ offw,   // [27][64][3][3]
    const float* __restrict__ offb)   // [27]
{
    extern __shared__ float wsh[];    // 576 * 28 floats = 64512 B
    int b = blockIdx.x >> 7;
    int h = blockIdx.x & 127;
    int w = threadIdx.x;

    // offw[j][ct] -> wsh[ct*28 + j]
    for (int i = threadIdx.x; i < 27*CC*KK9; i += blockDim.x) {
        int j  = i / (CC*KK9);
        int ct = i % (CC*KK9);
        wsh[ct*28 + j] = offw[i];
    }
    __syncthreads();

    float acc[28];
    #pragma unroll
    for (int j = 0; j < 27; j++) acc[j] = offb[j];
    acc[27] = 0.f;

    const float* xb = x + b*CC*HWSZ;
    for (int c = 0; c < CC; c++) {
        float xv[9];
        const float* xp = xb + c*HWSZ;
        #pragma unroll
        for (int ki = 0; ki < 3; ki++) {
            int y = h - 1 + ki;
            bool yok = ((unsigned)y < HH);
            #pragma unroll
            for (int kj = 0; kj < 3; kj++) {
                int xx = w - 1 + kj;
                bool ok = yok && ((unsigned)xx < WW);
                xv[ki*3+kj] = ok ? __ldg(xp + y*WW + xx) : 0.f;
            }
        }
        const float* wc = wsh + c*KK9*28;
        #pragma unroll
        for (int tap = 0; tap < 9; tap++) {
            float v = xv[tap];
            const float4* wt4 = (const float4*)(wc + tap*28);
            #pragma unroll
            for (int j4 = 0; j4 < 7; j4++) {
                float4 ww = wt4[j4];
                acc[j4*4+0] += v*ww.x;
                acc[j4*4+1] += v*ww.y;
                acc[j4*4+2] += v*ww.z;
                acc[j4*4+3] += v*ww.w;
            }
        }
    }

    // derive sample indices + weights
    int pix = h*WW + w;
    long base = (long)(b*HWSZ + pix) * KK9;
    #pragma unroll
    for (int k = 0; k < 9; k++) {
        int ki = k / 3, kj = k % 3;
        float py = (float)(h - 1 + ki) + acc[k];
        float px = (float)(w - 1 + kj) + acc[9+k];
        float m  = 1.f / (1.f + __expf(-acc[18+k]));
        float y0f = floorf(py), x0f = floorf(px);
        float wy = py - y0f, wx = px - x0f;
        int y0 = (int)y0f, x0 = (int)x0f;
        int y1 = y0 + 1,  x1 = x0 + 1;
        bool v0y = ((unsigned)y0 < HH), v1y = ((unsigned)y1 < HH);
        bool v0x = ((unsigned)x0 < WW), v1x = ((unsigned)x1 < WW);
        float w00 = (v0y && v0x) ? (1.f-wy)*(1.f-wx)*m : 0.f;
        float w01 = (v0y && v1x) ? (1.f-wy)*wx*m       : 0.f;
        float w10 = (v1y && v0x) ? wy*(1.f-wx)*m       : 0.f;
        float w11 = (v1y && v1x) ? wy*wx*m             : 0.f;
        int cy0 = min(max(y0,0),HH-1), cy1 = min(max(y1,0),HH-1);
        int cx0 = min(max(x0,0),WW-1), cx1 = min(max(x1,0),WW-1);
        g_sidx[base+k] = make_int4(cy0*WW+cx0, cy0*WW+cx1, cy1*WW+cx0, cy1*WW+cx1);
        g_swgt[base+k] = make_float4(w00, w01, w10, w11);
    }
}

// ---------------- K2: sample + GEMM --------------------------------------------
// CTA = (b, h, half-row of 64 pixels). 256 threads. 4x4 register tile per thread.
// smem: Wsh[144][64] | Ssh[144][64] | sIdx[576] int4 | sWgt[576] float4 = 90 KB
__global__ __launch_bounds__(256) void main_kernel(
    const float* __restrict__ x,
    const float* __restrict__ bias,
    float* __restrict__ out)
{
    extern __shared__ float sm[];
    float*  Wsh  = sm;                       // 9216 floats
    float*  Ssh  = sm + KKC*PIX;             // 9216 floats
    int4*   sIdx = (int4*)(sm + 2*KKC*PIX);  // 576 int4
    float4* sWgt = (float4*)(sm + 2*KKC*PIX + 576*4);

    int cta = blockIdx.x;
    int b   = cta >> 8;
    int rem = cta & 255;
    int h   = rem >> 1;
    int w0  = (rem & 1) << 6;
    int pix0 = h*WW + w0;
    int t = threadIdx.x;

    { // stage per-pixel sample metadata
        long gbase = (long)(b*HWSZ + pix0) * KK9;
        for (int i = t; i < PIX*KK9; i += 256) {
            sIdx[i] = g_sidx[gbase + i];
            sWgt[i] = g_swgt[gbase + i];
        }
    }

    float acc[4][4];
    #pragma unroll
    for (int i = 0; i < 4; i++)
        #pragma unroll
        for (int j = 0; j < 4; j++) acc[i][j] = 0.f;

    int tx = t & 15;    // o-tile
    int ty = t >> 4;    // p-tile
    int p  = t & 63;    // sampling: pixel
    int kq = t >> 6;    // sampling: row phase 0..3

    const float* xb = x + b*CC*HWSZ;

    for (int cc = 0; cc < CC/CCH; cc++) {
        __syncthreads();   // sIdx ready (iter 0) / previous GEMM reads done

        // load W chunk (contiguous in g_wt)
        const float4* gw = (const float4*)(g_wt + cc*KKC*OO);
        float4* wsh4 = (float4*)Wsh;
        #pragma unroll
        for (int i = 0; i < 9; i++)
            wsh4[t + i*256] = gw[t + i*256];

        // sampling: fill Ssh[144][64], 36 samples per thread
        #pragma unroll 4
        for (int it = 0; it < 36; it++) {
            int kk = kq + it*4;
            int ci = kk / 9;
            int k  = kk - ci*9;
            const float* xp = xb + (cc*CCH + ci)*HWSZ;
            int4   id = sIdx[p*KK9 + k];
            float4 wv = sWgt[p*KK9 + k];
            float s = wv.x*__ldg(xp+id.x) + wv.y*__ldg(xp+id.y)
                    + wv.z*__ldg(xp+id.z) + wv.w*__ldg(xp+id.w);
            Ssh[kk*PIX + p] = s;
        }
        __syncthreads();

        // GEMM: acc[4][4] += W[64 x 144] * S[144 x 64] tile
        #pragma unroll 4
        for (int kk = 0; kk < KKC; kk++) {
            float4 wv = *(const float4*)&Wsh[kk*OO  + tx*4];
            float4 sv = *(const float4*)&Ssh[kk*PIX + ty*4];
            acc[0][0] += wv.x*sv.x; acc[0][1] += wv.x*sv.y;
            acc[0][2] += wv.x*sv.z; acc[0][3] += wv.x*sv.w;
            acc[1][0] += wv.y*sv.x; acc[1][1] += wv.y*sv.y;
            acc[1][2] += wv.y*sv.z; acc[1][3] += wv.y*sv.w;
            acc[2][0] += wv.z*sv.x; acc[2][1] += wv.z*sv.y;
            acc[2][2] += wv.z*sv.z; acc[2][3] += wv.z*sv.w;
            acc[3][0] += wv.w*sv.x; acc[3][1] += wv.w*sv.y;
            acc[3][2] += wv.w*sv.z; acc[3][3] += wv.w*sv.w;
        }
    }

    // epilogue
    #pragma unroll
    for (int i = 0; i < 4; i++) {
        int o = tx*4 + i;
        float bv = bias[o];
        float4 r = make_float4(acc[i][0]+bv, acc[i][1]+bv, acc[i][2]+bv, acc[i][3]+bv);
        *(float4*)&out[(long)(b*OO + o)*HWSZ + pix0 + ty*4] = r;
    }
}

// ---------------- launch --------------------------------------------------------
extern "C" void kernel_launch(void* const* d_in, const int* in_sizes, int n_in,
                              void* d_out, int out_size)
{
    // identify inputs by element count (robust to ordering)
    const float *x = 0, *wt = 0, *bs = 0, *ow = 0, *ob = 0;
    for (int i = 0; i < n_in; i++) {
        switch (in_sizes[i]) {
            case BB*CC*HWSZ:   x  = (const float*)d_in[i]; break; // 2097152
            case OO*CC*KK9:    wt = (const float*)d_in[i]; break; // 36864
            case OO:           bs = (const float*)d_in[i]; break; // 64
            case 27*CC*KK9:    ow = (const float*)d_in[i]; break; // 15552
            case 27:           ob = (const float*)d_in[i]; break; // 27
        }
    }
    float* out = (float*)d_out;

    const int smem1 = 576*28*4;                              // 64512 B
    const int smem2 = (2*KKC*PIX + 576*4 + 576*4) * 4;       // 92160 B
    cudaFuncSetAttribute(offset_kernel, cudaFuncAttributeMaxDynamicSharedMemorySize, smem1);
    cudaFuncSetAttribute(main_kernel,  cudaFuncAttributeMaxDynamicSharedMemorySize, smem2);

    transpose_w_kernel<<<(OO*CC*KK9 + 255)/256, 256>>>(wt);
    offset_kernel<<<BB*HH, 128, smem1>>>(x, ow, ob);
    main_kernel<<<BB*HH*2, 256, smem2>>>(x, bs, out);
}

// round 6
// speedup vs baseline: 1.0232x; 1.0232x over previous
#include <cuda_runtime.h>

#define HH 128
#define WW 128
#define CC 64
#define OO 64
#define BB 2
#define KK9 9
#define HWSZ (HH*WW)

#define PIX 64          // pixels per CTA in main kernel
#define CCH 16          // channels per chunk
#define KKC (CCH*KK9)   // 144 rows per chunk

typedef unsigned long long ull;

// ---------------- f32x2 packed-FMA helpers -------------------------------------
__device__ __forceinline__ ull pack2(float a, float b) {
    ull r; asm("mov.b64 %0, {%1, %2};" : "=l"(r) : "f"(a), "f"(b)); return r;
}
__device__ __forceinline__ ull bcast2(float a) {
    ull r; asm("mov.b64 %0, {%1, %1};" : "=l"(r) : "f"(a)); return r;
}
__device__ __forceinline__ void ffma2(ull& d, ull a, ull b) {
    asm("fma.rn.f32x2 %0, %1, %2, %0;" : "+l"(d) : "l"(a), "l"(b));
}
__device__ __forceinline__ float lo2(ull v) { return __uint_as_float((unsigned)v); }
__device__ __forceinline__ float hi2(ull v) { return __uint_as_float((unsigned)(v >> 32)); }

// ---------------- scratch (__device__ globals: no allocation allowed) ----------
__device__ int4   g_sidx[BB*HWSZ*KK9];   // clamped gather indices per (b,pix,k)
__device__ float4 g_swgt[BB*HWSZ*KK9];   // mask-folded bilinear corner weights
__device__ float  g_wt[CC*KK9*OO];       // weight transposed to [c*9+k][o]

// ---------------- K1: weight transpose + offset conv + bilinear precompute -----
// CTA = (b, h) row, 128 threads = w. Each thread: 27 conv outputs (14 f32x2).
// smem: offset weights reorganized [c][tap][28] (27 used, padded for float4).
__global__ __launch_bounds__(128) void offset_kernel(
    const float* __restrict__ x,
    const float* __restrict__ wsrc,   // [64][64][3][3]  main conv weight
    const float* __restrict__ offw,   // [27][64][3][3]
    const float* __restrict__ offb)   // [27]
{
    extern __shared__ float wsh[];    // 576 * 28 floats = 64512 B
    int b = blockIdx.x >> 7;
    int h = blockIdx.x & 127;
    int w = threadIdx.x;

    // fold former transpose kernel: wsrc[o][ck] -> g_wt[ck][o] (grid-stride)
    for (int i = blockIdx.x * 128 + threadIdx.x; i < OO*CC*KK9; i += 256*128) {
        int o  = i / (CC*KK9);
        int ck = i % (CC*KK9);
        g_wt[ck*OO + o] = wsrc[i];
    }

    // offw[j][ct] -> wsh[ct*28 + j]
    for (int i = threadIdx.x; i < 27*CC*KK9; i += blockDim.x) {
        int j  = i / (CC*KK9);
        int ct = i % (CC*KK9);
        wsh[ct*28 + j] = offw[i];
    }
    __syncthreads();

    ull acc2[14];
    #pragma unroll
    for (int i = 0; i < 13; i++) acc2[i] = pack2(offb[2*i], offb[2*i+1]);
    acc2[13] = pack2(offb[26], 0.f);

    const float* xb = x + b*CC*HWSZ;
    for (int c = 0; c < CC; c++) {
        float xv[9];
        const float* xp = xb + c*HWSZ;
        #pragma unroll
        for (int ki = 0; ki < 3; ki++) {
            int y = h - 1 + ki;
            bool yok = ((unsigned)y < HH);
            #pragma unroll
            for (int kj = 0; kj < 3; kj++) {
                int xx = w - 1 + kj;
                bool ok = yok && ((unsigned)xx < WW);
                xv[ki*3+kj] = ok ? __ldg(xp + y*WW + xx) : 0.f;
            }
        }
        const float* wc = wsh + c*KK9*28;
        #pragma unroll
        for (int tap = 0; tap < 9; tap++) {
            ull xb2 = bcast2(xv[tap]);
            const ulonglong2* wt2 = (const ulonglong2*)(wc + tap*28);
            #pragma unroll
            for (int j2 = 0; j2 < 7; j2++) {
                ulonglong2 ww = wt2[j2];
                ffma2(acc2[j2*2    ], xb2, ww.x);
                ffma2(acc2[j2*2 + 1], xb2, ww.y);
            }
        }
    }

    // unpack accumulators
    float acc[27];
    #pragma unroll
    for (int j = 0; j < 27; j++)
        acc[j] = (j & 1) ? hi2(acc2[j >> 1]) : lo2(acc2[j >> 1]);

    // derive sample indices + weights
    int pix = h*WW + w;
    long base = (long)(b*HWSZ + pix) * KK9;
    #pragma unroll
    for (int k = 0; k < 9; k++) {
        int ki = k / 3, kj = k % 3;
        float py = (float)(h - 1 + ki) + acc[k];
        float px = (float)(w - 1 + kj) + acc[9+k];
        float m  = 1.f / (1.f + __expf(-acc[18+k]));
        float y0f = floorf(py), x0f = floorf(px);
        float wy = py - y0f, wx = px - x0f;
        int y0 = (int)y0f, x0 = (int)x0f;
        int y1 = y0 + 1,  x1 = x0 + 1;
        bool v0y = ((unsigned)y0 < HH), v1y = ((unsigned)y1 < HH);
        bool v0x = ((unsigned)x0 < WW), v1x = ((unsigned)x1 < WW);
        float w00 = (v0y && v0x) ? (1.f-wy)*(1.f-wx)*m : 0.f;
        float w01 = (v0y && v1x) ? (1.f-wy)*wx*m       : 0.f;
        float w10 = (v1y && v0x) ? wy*(1.f-wx)*m       : 0.f;
        float w11 = (v1y && v1x) ? wy*wx*m             : 0.f;
        int cy0 = min(max(y0,0),HH-1), cy1 = min(max(y1,0),HH-1);
        int cx0 = min(max(x0,0),WW-1), cx1 = min(max(x1,0),WW-1);
        g_sidx[base+k] = make_int4(cy0*WW+cx0, cy0*WW+cx1, cy1*WW+cx0, cy1*WW+cx1);
        g_swgt[base+k] = make_float4(w00, w01, w10, w11);
    }
}

// ---------------- K2: sample + GEMM (f32x2) ------------------------------------
// CTA = (b, h, half-row of 64 pixels). 256 threads. 4x4 register tile per thread,
// held as 4x2 packed f32x2 pairs.
// smem: Wsh[144][64] | Ssh[144][64] | sIdx[576] int4 | sWgt[576] float4 = 90 KB
__global__ __launch_bounds__(256) void main_kernel(
    const float* __restrict__ x,
    const float* __restrict__ bias,
    float* __restrict__ out)
{
    extern __shared__ float sm[];
    float*  Wsh  = sm;                       // 9216 floats
    float*  Ssh  = sm + KKC*PIX;             // 9216 floats
    int4*   sIdx = (int4*)(sm + 2*KKC*PIX);  // 576 int4
    float4* sWgt = (float4*)(sm + 2*KKC*PIX + 576*4);

    int cta = blockIdx.x;
    int b   = cta >> 8;
    int rem = cta & 255;
    int h   = rem >> 1;
    int w0  = (rem & 1) << 6;
    int pix0 = h*WW + w0;
    int t = threadIdx.x;

    { // stage per-pixel sample metadata
        long gbase = (long)(b*HWSZ + pix0) * KK9;
        for (int i = t; i < PIX*KK9; i += 256) {
            sIdx[i] = g_sidx[gbase + i];
            sWgt[i] = g_swgt[gbase + i];
        }
    }

    ull acc2[4][2];
    #pragma unroll
    for (int i = 0; i < 4; i++) {
        acc2[i][0] = 0ull; acc2[i][1] = 0ull;
    }

    int tx = t & 15;    // o-tile
    int ty = t >> 4;    // p-tile
    int p  = t & 63;    // sampling: pixel
    int kq = t >> 6;    // sampling: row phase 0..3

    const float* xb = x + b*CC*HWSZ;

    for (int cc = 0; cc < CC/CCH; cc++) {
        __syncthreads();   // sIdx ready (iter 0) / previous GEMM reads done

        // load W chunk (contiguous in g_wt)
        const float4* gw = (const float4*)(g_wt + cc*KKC*OO);
        float4* wsh4 = (float4*)Wsh;
        #pragma unroll
        for (int i = 0; i < 9; i++)
            wsh4[t + i*256] = gw[t + i*256];

        // sampling: fill Ssh[144][64], 36 samples per thread
        #pragma unroll 4
        for (int it = 0; it < 36; it++) {
            int kk = kq + it*4;
            int ci = kk / 9;
            int k  = kk - ci*9;
            const float* xp = xb + (cc*CCH + ci)*HWSZ;
            int4   id = sIdx[p*KK9 + k];
            float4 wv = sWgt[p*KK9 + k];
            float s = wv.x*__ldg(xp+id.x) + wv.y*__ldg(xp+id.y)
                    + wv.z*__ldg(xp+id.z) + wv.w*__ldg(xp+id.w);
            Ssh[kk*PIX + p] = s;
        }
        __syncthreads();

        // GEMM: acc += W[64 x 144] * S[144 x 64] tile, packed f32x2
        #pragma unroll 4
        for (int kk = 0; kk < KKC; kk++) {
            float4     wv = *(const float4*)&Wsh[kk*OO  + tx*4];
            ulonglong2 sv = *(const ulonglong2*)&Ssh[kk*PIX + ty*4];
            ull w0b = bcast2(wv.x);
            ull w1b = bcast2(wv.y);
            ull w2b = bcast2(wv.z);
            ull w3b = bcast2(wv.w);
            ffma2(acc2[0][0], w0b, sv.x); ffma2(acc2[0][1], w0b, sv.y);
            ffma2(acc2[1][0], w1b, sv.x); ffma2(acc2[1][1], w1b, sv.y);
            ffma2(acc2[2][0], w2b, sv.x); ffma2(acc2[2][1], w2b, sv.y);
            ffma2(acc2[3][0], w3b, sv.x); ffma2(acc2[3][1], w3b, sv.y);
        }
    }

    // epilogue
    #pragma unroll
    for (int i = 0; i < 4; i++) {
        int o = tx*4 + i;
        float bv = bias[o];
        float4 r = make_float4(lo2(acc2[i][0]) + bv, hi2(acc2[i][0]) + bv,
                               lo2(acc2[i][1]) + bv, hi2(acc2[i][1]) + bv);
        *(float4*)&out[(long)(b*OO + o)*HWSZ + pix0 + ty*4] = r;
    }
}

// ---------------- launch --------------------------------------------------------
extern "C" void kernel_launch(void* const* d_in, const int* in_sizes, int n_in,
                              void* d_out, int out_size)
{
    // identify inputs by element count (robust to ordering)
    const float *x = 0, *wt = 0, *bs = 0, *ow = 0, *ob = 0;
    for (int i = 0; i < n_in; i++) {
        switch (in_sizes[i]) {
            case BB*CC*HWSZ:   x  = (const float*)d_in[i]; break; // 2097152
            case OO*CC*KK9:    wt = (const float*)d_in[i]; break; // 36864
            case OO:           bs = (const float*)d_in[i]; break; // 64
            case 27*CC*KK9:    ow = (const float*)d_in[i]; break; // 15552
            case 27:           ob = (const float*)d_in[i]; break; // 27
        }
    }
    float* out = (float*)d_out;

    const int smem1 = 576*28*4;                              // 64512 B
    const int smem2 = (2*KKC*PIX + 576*4 + 576*4) * 4;       // 92160 B
    cudaFuncSetAttribute(offset_kernel, cudaFuncAttributeMaxDynamicSharedMemorySize, smem1);
    cudaFuncSetAttribute(main_kernel,  cudaFuncAttributeMaxDynamicSharedMemorySize, smem2);

    offset_kernel<<<BB*HH, 128, smem1>>>(x, wt, ow, ob);
    main_kernel<<<BB*HH*2, 256, smem2>>>(x, bs, out);
}

// round 7
// speedup vs baseline: 1.1929x; 1.1658x over previous
#include <cuda_runtime.h>

#define HH 128
#define WW 128
#define CC 64
#define OO 64
#define BB 2
#define KK9 9
#define HWSZ (HH*WW)

#define PIX 64          // pixels per CTA in main kernel
#define RKC 64          // rows per chunk in main kernel (= CC, one tap per chunk)

typedef unsigned long long ull;

// ---------------- f32x2 packed-FMA helpers -------------------------------------
__device__ __forceinline__ ull pack2(float a, float b) {
    ull r; asm("mov.b64 %0, {%1, %2};" : "=l"(r) : "f"(a), "f"(b)); return r;
}
__device__ __forceinline__ ull bcast2(float a) {
    ull r; asm("mov.b64 %0, {%1, %1};" : "=l"(r) : "f"(a)); return r;
}
__device__ __forceinline__ void ffma2(ull& d, ull a, ull b) {
    asm("fma.rn.f32x2 %0, %1, %2, %0;" : "+l"(d) : "l"(a), "l"(b));
}
__device__ __forceinline__ float lo2(ull v) { return __uint_as_float((unsigned)v); }
__device__ __forceinline__ float hi2(ull v) { return __uint_as_float((unsigned)(v >> 32)); }

// ---------------- scratch (__device__ globals: no allocation allowed) ----------
__device__ int4   g_sidx[BB*HWSZ*KK9];   // clamped gather indices per (b,pix,k)
__device__ float4 g_swgt[BB*HWSZ*KK9];   // mask-folded bilinear corner weights
__device__ float  g_wt[KK9*CC*OO];       // weight reordered to [k*64+c][o]

// ---------------- K1: weight transpose + offset conv + bilinear precompute -----
// CTA = (b, h) row, 128 threads = w. Each thread: 27 conv outputs (14 f32x2).
// smem: offset weights reorganized [c][tap][28] (27 used, padded for float4).
__global__ __launch_bounds__(128) void offset_kernel(
    const float* __restrict__ x,
    const float* __restrict__ wsrc,   // [64][64][3][3]  main conv weight
    const float* __restrict__ offw,   // [27][64][3][3]
    const float* __restrict__ offb)   // [27]
{
    extern __shared__ float wsh[];    // 576 * 28 floats = 64512 B
    int b = blockIdx.x >> 7;
    int h = blockIdx.x & 127;
    int w = threadIdx.x;

    // weight reorder: wsrc[o][c][k] -> g_wt[(k*CC+c)*OO + o]  (grid-stride)
    for (int i = blockIdx.x * 128 + threadIdx.x; i < OO*CC*KK9; i += 256*128) {
        int o = i / (CC*KK9);
        int r = i % (CC*KK9);
        int c = r / KK9;
        int k = r % KK9;
        g_wt[(k*CC + c)*OO + o] = wsrc[i];
    }

    // offw[j][ct] -> wsh[ct*28 + j]
    for (int i = threadIdx.x; i < 27*CC*KK9; i += blockDim.x) {
        int j  = i / (CC*KK9);
        int ct = i % (CC*KK9);
        wsh[ct*28 + j] = offw[i];
    }
    __syncthreads();

    ull acc2[14];
    #pragma unroll
    for (int i = 0; i < 13; i++) acc2[i] = pack2(offb[2*i], offb[2*i+1]);
    acc2[13] = pack2(offb[26], 0.f);

    const float* xb = x + b*CC*HWSZ;
    for (int c = 0; c < CC; c++) {
        float xv[9];
        const float* xp = xb + c*HWSZ;
        #pragma unroll
        for (int ki = 0; ki < 3; ki++) {
            int y = h - 1 + ki;
            bool yok = ((unsigned)y < HH);
            #pragma unroll
            for (int kj = 0; kj < 3; kj++) {
                int xx = w - 1 + kj;
                bool ok = yok && ((unsigned)xx < WW);
                xv[ki*3+kj] = ok ? __ldg(xp + y*WW + xx) : 0.f;
            }
        }
        const float* wc = wsh + c*KK9*28;
        #pragma unroll
        for (int tap = 0; tap < 9; tap++) {
            ull xb2 = bcast2(xv[tap]);
            const ulonglong2* wt2 = (const ulonglong2*)(wc + tap*28);
            #pragma unroll
            for (int j2 = 0; j2 < 7; j2++) {
                ulonglong2 ww = wt2[j2];
                ffma2(acc2[j2*2    ], xb2, ww.x);
                ffma2(acc2[j2*2 + 1], xb2, ww.y);
            }
        }
    }

    // unpack accumulators
    float acc[27];
    #pragma unroll
    for (int j = 0; j < 27; j++)
        acc[j] = (j & 1) ? hi2(acc2[j >> 1]) : lo2(acc2[j >> 1]);

    // derive sample indices + weights
    int pix = h*WW + w;
    long base = (long)(b*HWSZ + pix) * KK9;
    #pragma unroll
    for (int k = 0; k < 9; k++) {
        int ki = k / 3, kj = k % 3;
        float py = (float)(h - 1 + ki) + acc[k];
        float px = (float)(w - 1 + kj) + acc[9+k];
        float m  = 1.f / (1.f + __expf(-acc[18+k]));
        float y0f = floorf(py), x0f = floorf(px);
        float wy = py - y0f, wx = px - x0f;
        int y0 = (int)y0f, x0 = (int)x0f;
        int y1 = y0 + 1,  x1 = x0 + 1;
        bool v0y = ((unsigned)y0 < HH), v1y = ((unsigned)y1 < HH);
        bool v0x = ((unsigned)x0 < WW), v1x = ((unsigned)x1 < WW);
        float w00 = (v0y && v0x) ? (1.f-wy)*(1.f-wx)*m : 0.f;
        float w01 = (v0y && v1x) ? (1.f-wy)*wx*m       : 0.f;
        float w10 = (v1y && v0x) ? wy*(1.f-wx)*m       : 0.f;
        float w11 = (v1y && v1x) ? wy*wx*m             : 0.f;
        int cy0 = min(max(y0,0),HH-1), cy1 = min(max(y1,0),HH-1);
        int cx0 = min(max(x0,0),WW-1), cx1 = min(max(x1,0),WW-1);
        g_sidx[base+k] = make_int4(cy0*WW+cx0, cy0*WW+cx1, cy1*WW+cx0, cy1*WW+cx1);
        g_swgt[base+k] = make_float4(w00, w01, w10, w11);
    }
}

// ---------------- K2: sample + GEMM (f32x2), k-major chunks --------------------
// CTA = (b, h, half-row of 64 pixels). 256 threads. 9 chunks, one kernel tap
// each: chunk k covers rows r = k*64 + c (all 64 channels at fixed tap).
// Sample metadata for the chunk = ONE (int4,float4) per pixel -> registers.
// smem: Wsh[64][64] | Ssh[64][64] = 32 KB  -> 5 CTAs/SM.
__global__ __launch_bounds__(256, 5) void main_kernel(
    const float* __restrict__ x,
    const float* __restrict__ bias,
    float* __restrict__ out)
{
    extern __shared__ float sm[];
    float* Wsh = sm;                 // 4096 floats
    float* Ssh = sm + RKC*PIX;       // 4096 floats

    int cta = blockIdx.x;
    int b   = cta >> 8;
    int rem = cta & 255;
    int h   = rem >> 1;
    int w0  = (rem & 1) << 6;
    int pix0 = h*WW + w0;
    int t = threadIdx.x;

    ull acc2[4][2];
    #pragma unroll
    for (int i = 0; i < 4; i++) { acc2[i][0] = 0ull; acc2[i][1] = 0ull; }

    int tx  = t & 15;    // GEMM: o-tile
    int ty  = t >> 4;    // GEMM: p-tile
    int p   = t & 63;    // sampling: pixel
    int cph = t >> 6;    // sampling: channel phase 0..3

    const float* xb = x + b*CC*HWSZ;
    long mbase = ((long)(b*HWSZ + pix0 + p)) * KK9;

    for (int k = 0; k < KK9; k++) {
        // per-chunk metadata: one sample point per pixel (registers, no smem)
        int4   id = __ldg(&g_sidx[mbase + k]);
        float4 wv = __ldg(&g_swgt[mbase + k]);

        __syncthreads();   // previous GEMM reads done

        // load W chunk: g_wt rows k*64..k*64+63, contiguous 16 KB
        {
            const float4* gw = (const float4*)(g_wt + k*CC*OO);
            float4* wsh4 = (float4*)Wsh;
            #pragma unroll
            for (int i = 0; i < 4; i++)
                wsh4[t + i*256] = gw[t + i*256];
        }

        // sampling: 16 channels per thread at the fixed sample point
        #pragma unroll 8
        for (int j = 0; j < 16; j++) {
            int c = cph + j*4;
            const float* xp = xb + c*HWSZ;
            float s = wv.x*__ldg(xp+id.x) + wv.y*__ldg(xp+id.y)
                    + wv.z*__ldg(xp+id.z) + wv.w*__ldg(xp+id.w);
            Ssh[c*PIX + p] = s;
        }
        __syncthreads();

        // GEMM: acc += W[64 x 64] * S[64 x 64] tile, packed f32x2
        #pragma unroll 4
        for (int c = 0; c < RKC; c++) {
            float4     wr = *(const float4*)&Wsh[c*OO  + tx*4];
            ulonglong2 sv = *(const ulonglong2*)&Ssh[c*PIX + ty*4];
            ull w0b = bcast2(wr.x);
            ull w1b = bcast2(wr.y);
            ull w2b = bcast2(wr.z);
            ull w3b = bcast2(wr.w);
            ffma2(acc2[0][0], w0b, sv.x); ffma2(acc2[0][1], w0b, sv.y);
            ffma2(acc2[1][0], w1b, sv.x); ffma2(acc2[1][1], w1b, sv.y);
            ffma2(acc2[2][0], w2b, sv.x); ffma2(acc2[2][1], w2b, sv.y);
            ffma2(acc2[3][0], w3b, sv.x); ffma2(acc2[3][1], w3b, sv.y);
        }
    }

    // epilogue
    #pragma unroll
    for (int i = 0; i < 4; i++) {
        int o = tx*4 + i;
        float bv = bias[o];
        float4 r = make_float4(lo2(acc2[i][0]) + bv, hi2(acc2[i][0]) + bv,
                               lo2(acc2[i][1]) + bv, hi2(acc2[i][1]) + bv);
        *(float4*)&out[(long)(b*OO + o)*HWSZ + pix0 + ty*4] = r;
    }
}

// ---------------- launch --------------------------------------------------------
extern "C" void kernel_launch(void* const* d_in, const int* in_sizes, int n_in,
                              void* d_out, int out_size)
{
    // identify inputs by element count (robust to ordering)
    const float *x = 0, *wt = 0, *bs = 0, *ow = 0, *ob = 0;
    for (int i = 0; i < n_in; i++) {
        switch (in_sizes[i]) {
            case BB*CC*HWSZ:   x  = (const float*)d_in[i]; break; // 2097152
            case OO*CC*KK9:    wt = (const float*)d_in[i]; break; // 36864
            case OO:           bs = (const float*)d_in[i]; break; // 64
            case 27*CC*KK9:    ow = (const float*)d_in[i]; break; // 15552
            case 27:           ob = (const float*)d_in[i]; break; // 27
        }
    }
    float* out = (float*)d_out;

    const int smem1 = 576*28*4;          // 64512 B
    const int smem2 = 2*RKC*PIX*4;       // 32768 B
    cudaFuncSetAttribute(offset_kernel, cudaFuncAttributeMaxDynamicSharedMemorySize, smem1);
    cudaFuncSetAttribute(main_kernel,  cudaFuncAttributeMaxDynamicSharedMemorySize, smem2);

    offset_kernel<<<BB*HH, 128, smem1>>>(x, wt, ow, ob);
    main_kernel<<<BB*HH*2, 256, smem2>>>(x, bs, out);
}

// round 8
// speedup vs baseline: 1.2993x; 1.0892x over previous
#include <cuda_runtime.h>

#define HH 128
#define WW 128
#define CC 64
#define OO 64
#define BB 2
#define KK9 9
#define HWSZ (HH*WW)

#define PIX 64          // pixels per main-kernel CTA
#define CH  32          // channels per main-kernel CTA (split-K half)

typedef unsigned long long ull;

// ---------------- f32x2 packed helpers -----------------------------------------
__device__ __forceinline__ ull pack2(float a, float b) {
    ull r; asm("mov.b64 %0, {%1, %2};" : "=l"(r) : "f"(a), "f"(b)); return r;
}
__device__ __forceinline__ ull bcast2(float a) {
    ull r; asm("mov.b64 %0, {%1, %1};" : "=l"(r) : "f"(a)); return r;
}
__device__ __forceinline__ void ffma2(ull& d, ull a, ull b) {
    asm("fma.rn.f32x2 %0, %1, %2, %0;" : "+l"(d) : "l"(a), "l"(b));
}
__device__ __forceinline__ void fadd2(ull& d, ull a) {
    asm("add.rn.f32x2 %0, %0, %1;" : "+l"(d) : "l"(a));
}
__device__ __forceinline__ float lo2(ull v) { return __uint_as_float((unsigned)v); }
__device__ __forceinline__ float hi2(ull v) { return __uint_as_float((unsigned)(v >> 32)); }

// ---------------- scratch (__device__ globals) ---------------------------------
__device__ int4   g_sidx[BB*HWSZ*KK9];      // clamped gather indices per (b,pix,k)
__device__ float4 g_swgt[BB*HWSZ*KK9];      // mask-folded bilinear corner weights
__device__ float  g_wt[KK9*CC*OO];          // weight reordered to [k*64+c][o]
__device__ float  g_part[2][BB*OO*HWSZ];    // split-K partial outputs

// ---------------- K1: weight reorder + offset conv + bilinear precompute -------
// CTA = (b, h) row, 256 threads = (pixel w 0..127) x (channel half 0..1).
// Each thread: 27 conv outputs over its 32 channels; halves combined via smem.
__global__ __launch_bounds__(256) void offset_kernel(
    const float* __restrict__ x,
    const float* __restrict__ wsrc,   // [64][64][3][3]  main conv weight
    const float* __restrict__ offw,   // [27][64][3][3]
    const float* __restrict__ offb)   // [27]
{
    extern __shared__ float wsh[];    // 576*28 floats | ull part[128][14]
    ull* part = (ull*)(wsh + 576*28);

    int b = blockIdx.x >> 7;
    int h = blockIdx.x & 127;
    int t = threadIdx.x;
    int w     = t & 127;
    int chalf = t >> 7;

    // weight reorder: wsrc[o][c][k] -> g_wt[(k*CC+c)*OO + o]  (one shot, 256x256 >= 36864)
    {
        int i = blockIdx.x * 256 + t;
        if (i < OO*CC*KK9) {
            int o = i / (CC*KK9);
            int r = i % (CC*KK9);
            int c = r / KK9;
            int k = r % KK9;
            g_wt[(k*CC + c)*OO + o] = wsrc[i];
        }
    }

    // offw[j][ct] -> wsh[ct*28 + j]
    for (int i = t; i < 27*CC*KK9; i += 256) {
        int j  = i / (CC*KK9);
        int ct = i % (CC*KK9);
        wsh[ct*28 + j] = offw[i];
    }
    __syncthreads();

    ull acc2[14];
    if (chalf == 0) {
        #pragma unroll
        for (int i = 0; i < 13; i++) acc2[i] = pack2(offb[2*i], offb[2*i+1]);
        acc2[13] = pack2(offb[26], 0.f);
    } else {
        #pragma unroll
        for (int i = 0; i < 14; i++) acc2[i] = 0ull;
    }

    const float* xb = x + b*CC*HWSZ;
    int c0 = chalf * 32;
    for (int ci = 0; ci < 32; ci++) {
        int c = c0 + ci;
        float xv[9];
        const float* xp = xb + c*HWSZ;
        #pragma unroll
        for (int ki = 0; ki < 3; ki++) {
            int y = h - 1 + ki;
            bool yok = ((unsigned)y < HH);
            #pragma unroll
            for (int kj = 0; kj < 3; kj++) {
                int xx = w - 1 + kj;
                bool ok = yok && ((unsigned)xx < WW);
                xv[ki*3+kj] = ok ? __ldg(xp + y*WW + xx) : 0.f;
            }
        }
        const float* wc = wsh + c*KK9*28;
        #pragma unroll
        for (int tap = 0; tap < 9; tap++) {
            ull xb2 = bcast2(xv[tap]);
            const ulonglong2* wt2 = (const ulonglong2*)(wc + tap*28);
            #pragma unroll
            for (int j2 = 0; j2 < 7; j2++) {
                ulonglong2 ww = wt2[j2];
                ffma2(acc2[j2*2    ], xb2, ww.x);
                ffma2(acc2[j2*2 + 1], xb2, ww.y);
            }
        }
    }

    // combine halves: chalf 1 dumps to smem, chalf 0 adds + finalizes
    if (chalf == 1) {
        #pragma unroll
        for (int i = 0; i < 14; i++) part[w*14 + i] = acc2[i];
    }
    __syncthreads();
    if (chalf == 1) return;

    #pragma unroll
    for (int i = 0; i < 14; i++) fadd2(acc2[i], part[w*14 + i]);

    float acc[27];
    #pragma unroll
    for (int j = 0; j < 27; j++)
        acc[j] = (j & 1) ? hi2(acc2[j >> 1]) : lo2(acc2[j >> 1]);

    // derive sample indices + weights
    int pix = h*WW + w;
    long base = (long)(b*HWSZ + pix) * KK9;
    #pragma unroll
    for (int k = 0; k < 9; k++) {
        int ki = k / 3, kj = k % 3;
        float py = (float)(h - 1 + ki) + acc[k];
        float px = (float)(w - 1 + kj) + acc[9+k];
        float m  = 1.f / (1.f + __expf(-acc[18+k]));
        float y0f = floorf(py), x0f = floorf(px);
        float wy = py - y0f, wx = px - x0f;
        int y0 = (int)y0f, x0 = (int)x0f;
        int y1 = y0 + 1,  x1 = x0 + 1;
        bool v0y = ((unsigned)y0 < HH), v1y = ((unsigned)y1 < HH);
        bool v0x = ((unsigned)x0 < WW), v1x = ((unsigned)x1 < WW);
        float w00 = (v0y && v0x) ? (1.f-wy)*(1.f-wx)*m : 0.f;
        float w01 = (v0y && v1x) ? (1.f-wy)*wx*m       : 0.f;
        float w10 = (v1y && v0x) ? wy*(1.f-wx)*m       : 0.f;
        float w11 = (v1y && v1x) ? wy*wx*m             : 0.f;
        int cy0 = min(max(y0,0),HH-1), cy1 = min(max(y1,0),HH-1);
        int cx0 = min(max(x0,0),WW-1), cx1 = min(max(x1,0),WW-1);
        g_sidx[base+k] = make_int4(cy0*WW+cx0, cy0*WW+cx1, cy1*WW+cx0, cy1*WW+cx1);
        g_swgt[base+k] = make_float4(w00, w01, w10, w11);
    }
}

// ---------------- K2: sample + partial GEMM (f32x2), split-K -------------------
// CTA = (b, h, half-row, channel-half). 256 threads. 9 chunks of (tap, 32 ch).
// smem: Wsh[32][64] | Ssh[32][64] = 16 KB  -> 5 CTAs/SM, grid 1024.
__global__ __launch_bounds__(256, 5) void main_kernel(
    const float* __restrict__ x)
{
    extern __shared__ float sm[];
    float* Wsh = sm;                 // 2048 floats
    float* Ssh = sm + CH*PIX;        // 2048 floats

    int cta   = blockIdx.x;
    int chalf = cta & 1;
    int wh    = (cta >> 1) & 1;
    int h     = (cta >> 2) & 127;
    int b     = cta >> 9;
    int pix0  = h*WW + (wh << 6);
    int t = threadIdx.x;

    ull acc2[4][2];
    #pragma unroll
    for (int i = 0; i < 4; i++) { acc2[i][0] = 0ull; acc2[i][1] = 0ull; }

    int tx  = t & 15;    // GEMM: o-tile
    int ty  = t >> 4;    // GEMM: p-tile
    int p   = t & 63;    // sampling: pixel
    int cph = t >> 6;    // sampling: channel phase 0..3

    const float* xb = x + (b*CC + chalf*CH)*HWSZ;
    long mbase = ((long)(b*HWSZ + pix0 + p)) * KK9;

    for (int k = 0; k < KK9; k++) {
        // per-chunk metadata: one sample point per pixel (registers)
        int4   id = __ldg(&g_sidx[mbase + k]);
        float4 wv = __ldg(&g_swgt[mbase + k]);

        __syncthreads();   // previous GEMM reads done

        // load W chunk: rows (k, chalf half), contiguous 8 KB
        {
            const float4* gw = (const float4*)(g_wt + (k*CC + chalf*CH)*OO);
            float4* wsh4 = (float4*)Wsh;
            #pragma unroll
            for (int i = 0; i < 2; i++)
                wsh4[t + i*256] = gw[t + i*256];
        }

        // sampling: 8 channels per thread at the fixed sample point
        #pragma unroll 8
        for (int j = 0; j < 8; j++) {
            int c = cph + j*4;
            const float* xp = xb + c*HWSZ;
            float s = wv.x*__ldg(xp+id.x) + wv.y*__ldg(xp+id.y)
                    + wv.z*__ldg(xp+id.z) + wv.w*__ldg(xp+id.w);
            Ssh[c*PIX + p] = s;
        }
        __syncthreads();

        // partial GEMM: acc += W[32 x 64]^T-broadcast * S[32 x 64] tile
        #pragma unroll 4
        for (int c = 0; c < CH; c++) {
            float4     wr = *(const float4*)&Wsh[c*OO  + tx*4];
            ulonglong2 sv = *(const ulonglong2*)&Ssh[c*PIX + ty*4];
            ull w0b = bcast2(wr.x);
            ull w1b = bcast2(wr.y);
            ull w2b = bcast2(wr.z);
            ull w3b = bcast2(wr.w);
            ffma2(acc2[0][0], w0b, sv.x); ffma2(acc2[0][1], w0b, sv.y);
            ffma2(acc2[1][0], w1b, sv.x); ffma2(acc2[1][1], w1b, sv.y);
            ffma2(acc2[2][0], w2b, sv.x); ffma2(acc2[2][1], w2b, sv.y);
            ffma2(acc2[3][0], w3b, sv.x); ffma2(acc2[3][1], w3b, sv.y);
        }
    }

    // write partials (no bias here; K3 adds)
    float* dst = g_part[chalf];
    #pragma unroll
    for (int i = 0; i < 4; i++) {
        int o = tx*4 + i;
        float4 r = make_float4(lo2(acc2[i][0]), hi2(acc2[i][0]),
                               lo2(acc2[i][1]), hi2(acc2[i][1]));
        *(float4*)&dst[(long)(b*OO + o)*HWSZ + pix0 + ty*4] = r;
    }
}

// ---------------- K3: combine split-K partials + bias --------------------------
__global__ __launch_bounds__(256) void combine_kernel(
    const float* __restrict__ bias,
    float* __restrict__ out)
{
    int i = blockIdx.x * 256 + threadIdx.x;          // float4 index
    // element = i*4 ; o = (element >> 14) & 63  (HWSZ = 16384)
    int o = (i >> 12) & 63;
    float4 a = ((const float4*)g_part[0])[i];
    float4 c = ((const float4*)g_part[1])[i];
    float bv = __ldg(&bias[o]);
    float4 r = make_float4(a.x + c.x + bv, a.y + c.y + bv,
                           a.z + c.z + bv, a.w + c.w + bv);
    ((float4*)out)[i] = r;
}

// ---------------- launch --------------------------------------------------------
extern "C" void kernel_launch(void* const* d_in, const int* in_sizes, int n_in,
                              void* d_out, int out_size)
{
    // identify inputs by element count (robust to ordering)
    const float *x = 0, *wt = 0, *bs = 0, *ow = 0, *ob = 0;
    for (int i = 0; i < n_in; i++) {
        switch (in_sizes[i]) {
            case BB*CC*HWSZ:   x  = (const float*)d_in[i]; break; // 2097152
            case OO*CC*KK9:    wt = (const float*)d_in[i]; break; // 36864
            case OO:           bs = (const float*)d_in[i]; break; // 64
            case 27*CC*KK9:    ow = (const float*)d_in[i]; break; // 15552
            case 27:           ob = (const float*)d_in[i]; break; // 27
        }
    }
    float* out = (float*)d_out;

    const int smem1 = 576*28*4 + 128*14*8;   // 78848 B
    const int smem2 = 2*CH*PIX*4;            // 16384 B
    cudaFuncSetAttribute(offset_kernel, cudaFuncAttributeMaxDynamicSharedMemorySize, smem1);
    cudaFuncSetAttribute(main_kernel,  cudaFuncAttributeMaxDynamicSharedMemorySize, smem2);

    offset_kernel<<<BB*HH, 256, smem1>>>(x, wt, ow, ob);
    main_kernel<<<BB*HH*2*2, 256, smem2>>>(x);
    combine_kernel<<<(BB*OO*HWSZ/4)/256, 256>>>(bs, out);
}